// round 1
// baseline (speedup 1.0000x reference)
#include <cuda_runtime.h>
#include <math.h>

#define NN   100000
#define EE   1600000
#define FIN  700
#define HH   128
#define EPSV 1e-5f

// ---------------- scratch (static device globals; no runtime allocation) ---------
__device__ float g_h  [(size_t)NN * HH];
__device__ float g_hn [(size_t)NN * HH];
__device__ float g_agg[(size_t)NN * HH];
__device__ float g_z  [(size_t)NN * 64];
__device__ float g_denom[NN];
__device__ int   g_deg[NN];            // degree, then reused as scatter cursor
__device__ int   g_rowptr[NN + 1];
__device__ int   g_colidx[EE];
__device__ int   g_bsums[128];
__device__ float g_stats[256];         // [0..Hc) sum, [Hc..2Hc) sumsq
__device__ float g_ab[256];            // [0..Hc) scale A, [Hc..2Hc) offset B

// ---------------- CSR construction --------------------------------------------
__global__ void k_zero_deg() {
    int i = blockIdx.x * blockDim.x + threadIdx.x;
    if (i < NN) g_deg[i] = 0;
}

__global__ void k_count(const int* __restrict__ graph) {
    int e = blockIdx.x * blockDim.x + threadIdx.x;
    if (e < EE) atomicAdd(&g_deg[graph[2 * e + 1]], 1);
}

__global__ void k_scan1() {  // per-block inclusive scan of deg, 1024/block
    __shared__ int s[1024];
    int tid = threadIdx.x;
    int i = blockIdx.x * 1024 + tid;
    int v = (i < NN) ? g_deg[i] : 0;
    s[tid] = v;
    __syncthreads();
    #pragma unroll
    for (int off = 1; off < 1024; off <<= 1) {
        int t = (tid >= off) ? s[tid - off] : 0;
        __syncthreads();
        s[tid] += t;
        __syncthreads();
    }
    if (i < NN) g_rowptr[i + 1] = s[tid];
    if (tid == 1023) g_bsums[blockIdx.x] = s[1023];
}

__global__ void k_scan2() {  // exclusive scan of 98 block sums (serial; tiny)
    if (threadIdx.x == 0) {
        const int nb = (NN + 1023) / 1024;
        int acc = 0;
        for (int i = 0; i < nb; i++) { int t = g_bsums[i]; g_bsums[i] = acc; acc += t; }
    }
}

__global__ void k_scan3() {  // add block offsets; denom; reset deg as cursor
    int i = blockIdx.x * blockDim.x + threadIdx.x;
    if (i >= NN) return;
    g_rowptr[i + 1] += g_bsums[i >> 10];
    if (i == 0) g_rowptr[0] = 0;
    int d = g_deg[i];
    g_denom[i] = (float)((d > 1) ? d : 1);
    g_deg[i] = 0;
}

__global__ void k_fill(const int* __restrict__ graph) {
    int e = blockIdx.x * blockDim.x + threadIdx.x;
    if (e >= EE) return;
    int src = graph[2 * e + 0];
    int dst = graph[2 * e + 1];
    int pos = g_rowptr[dst] + atomicAdd(&g_deg[dst], 1);
    g_colidx[pos] = src;
}

// ---------------- SGEMM: C[M,NC] = A[M,K] @ B[K,NC], fp32 ----------------------
template <int BN, int TN>
__global__ __launch_bounds__(256) void sgemm(const float* __restrict__ A,
                                             const float* __restrict__ B,
                                             float* __restrict__ C,
                                             int M, int K, int NC) {
    constexpr int BM = 128, BK = 8, TM = 8;
    constexpr int TX = BN / TN;  // 16
    __shared__ float As[BK][BM];
    __shared__ float Bs[BK][BN];
    const int tid = threadIdx.x;
    const int tx = tid % TX;
    const int ty = tid / TX;
    const int row0 = blockIdx.y * BM;
    const int col0 = blockIdx.x * BN;

    float acc[TM][TN];
    #pragma unroll
    for (int i = 0; i < TM; i++)
        #pragma unroll
        for (int j = 0; j < TN; j++) acc[i][j] = 0.f;

    for (int kk = 0; kk < K; kk += BK) {
        {   // A tile: BM x BK, transposed into As[k][m]
            constexpr int NF4 = BM * BK / 4;  // 256
            #pragma unroll
            for (int t = tid; t < NF4; t += 256) {
                int r = t / (BK / 4);
                int q = t % (BK / 4);
                float4 v = make_float4(0.f, 0.f, 0.f, 0.f);
                int gr = row0 + r, gk = kk + q * 4;
                if (gr < M && gk < K)
                    v = *reinterpret_cast<const float4*>(A + (size_t)gr * K + gk);
                As[q * 4 + 0][r] = v.x;
                As[q * 4 + 1][r] = v.y;
                As[q * 4 + 2][r] = v.z;
                As[q * 4 + 3][r] = v.w;
            }
        }
        {   // B tile: BK x BN
            constexpr int NF4 = BK * BN / 4;  // 256 (BN=128) or 128 (BN=64)
            #pragma unroll
            for (int t = tid; t < NF4; t += 256) {
                int r = t / (BN / 4);
                int q = t % (BN / 4);
                float4 v = make_float4(0.f, 0.f, 0.f, 0.f);
                int gk = kk + r;
                if (gk < K)
                    v = *reinterpret_cast<const float4*>(B + (size_t)gk * NC + col0 + q * 4);
                *reinterpret_cast<float4*>(&Bs[r][q * 4]) = v;
            }
        }
        __syncthreads();
        #pragma unroll
        for (int k = 0; k < BK; k++) {
            float a[TM], b[TN];
            #pragma unroll
            for (int i = 0; i < TM; i++) a[i] = As[k][ty * TM + i];
            #pragma unroll
            for (int j = 0; j < TN; j++) b[j] = Bs[k][tx * TN + j];
            #pragma unroll
            for (int i = 0; i < TM; i++)
                #pragma unroll
                for (int j = 0; j < TN; j++) acc[i][j] = fmaf(a[i], b[j], acc[i][j]);
        }
        __syncthreads();
    }
    #pragma unroll
    for (int i = 0; i < TM; i++) {
        int gr = row0 + ty * TM + i;
        if (gr >= M) continue;
        #pragma unroll
        for (int j = 0; j < TN; j += 4) {
            float4 v = make_float4(acc[i][j], acc[i][j + 1], acc[i][j + 2], acc[i][j + 3]);
            *reinterpret_cast<float4*>(C + (size_t)gr * NC + col0 + tx * TN + j) = v;
        }
    }
}

// ---------------- neighbor aggregation (CSR gather, L2-resident) ---------------
__global__ void k_aggregate(const float* __restrict__ hn, float* __restrict__ agg) {
    int node = blockIdx.x;
    int c = threadIdx.x;  // 128 threads = H columns
    int s = g_rowptr[node];
    int e = g_rowptr[node + 1];
    float acc = 0.f;
    int p = s;
    for (; p + 1 < e; p += 2) {
        int n0 = __ldg(&g_colidx[p]);
        int n1 = __ldg(&g_colidx[p + 1]);
        acc += __ldg(&hn[(size_t)n0 * HH + c]) + __ldg(&hn[(size_t)n1 * HH + c]);
    }
    if (p < e) acc += __ldg(&hn[(size_t)g_colidx[p] * HH + c]);
    agg[(size_t)node * HH + c] = acc / g_denom[node];
}

// ---------------- bias+agg combine with fused BN stats -------------------------
__global__ void k_zero_stats() { g_stats[threadIdx.x] = 0.f; }

__global__ void k_combine(float* __restrict__ pre, const float* __restrict__ agg,
                          const float* __restrict__ bias, int M, int rows) {
    const int Hc = blockDim.x;
    int c = threadIdx.x;
    int r0 = blockIdx.x * rows;
    int r1 = min(r0 + rows, M);
    float bb = bias[c];
    float s = 0.f, s2 = 0.f;
    for (int r = r0; r < r1; r++) {
        size_t idx = (size_t)r * Hc + c;
        float v = pre[idx] + bb;
        if (agg) v += agg[idx];
        pre[idx] = v;
        s += v;
        s2 += v * v;
    }
    atomicAdd(&g_stats[c], s);
    atomicAdd(&g_stats[Hc + c], s2);
}

__global__ void k_finalize(const float* __restrict__ gamma, const float* __restrict__ beta, int M) {
    int c = threadIdx.x;
    int Hc = blockDim.x;
    float inv_m = 1.f / (float)M;
    float mean = g_stats[c] * inv_m;
    float var = g_stats[Hc + c] * inv_m - mean * mean;
    float a = gamma[c] * rsqrtf(var + EPSV);
    g_ab[c] = a;
    g_ab[Hc + c] = beta[c] - mean * a;
}

// normalize + relu (+ residual), float4-vectorized
__global__ void k_normalize(const float* __restrict__ pre, float* __restrict__ hout,
                            const float* __restrict__ resid, int total4, int Hc4) {
    int i = blockIdx.x * blockDim.x + threadIdx.x;
    if (i >= total4) return;
    int c4 = i % Hc4;
    float4 p = reinterpret_cast<const float4*>(pre)[i];
    float4 a = reinterpret_cast<const float4*>(g_ab)[c4];
    float4 b = reinterpret_cast<const float4*>(g_ab)[Hc4 + c4];
    float4 v;
    v.x = fmaf(p.x, a.x, b.x);
    v.y = fmaf(p.y, a.y, b.y);
    v.z = fmaf(p.z, a.z, b.z);
    v.w = fmaf(p.w, a.w, b.w);
    if (resid) {
        float4 r = reinterpret_cast<const float4*>(resid)[i];
        v.x += r.x; v.y += r.y; v.z += r.z; v.w += r.w;
    }
    v.x = fmaxf(v.x, 0.f); v.y = fmaxf(v.y, 0.f);
    v.z = fmaxf(v.z, 0.f); v.w = fmaxf(v.w, 0.f);
    reinterpret_cast<float4*>(hout)[i] = v;
}

// final: BN1 -> relu -> @W2 + b2, one warp per node
__global__ void k_output(const float* __restrict__ zpre, const float* __restrict__ W2,
                         const float* __restrict__ b2, float* __restrict__ out) {
    int gtid = blockIdx.x * blockDim.x + threadIdx.x;
    int node = gtid >> 5;
    int lane = gtid & 31;
    if (node >= NN) return;
    float acc = 0.f;
    #pragma unroll
    for (int j = lane; j < 64; j += 32) {
        float v = fmaf(zpre[(size_t)node * 64 + j], g_ab[j], g_ab[64 + j]);
        v = fmaxf(v, 0.f);
        acc += v * W2[j];
    }
    #pragma unroll
    for (int o = 16; o; o >>= 1) acc += __shfl_xor_sync(0xFFFFFFFFu, acc, o);
    if (lane == 0) out[node] = acc + b2[0];
}

// ---------------- host orchestration ------------------------------------------
extern "C" void kernel_launch(void* const* d_in, const int* in_sizes, int n_in,
                              void* d_out, int out_size) {
    const float* inputs   = (const float*)d_in[0];
    const int*   graph    = (const int*)  d_in[1];
    const float* Wself0   = (const float*)d_in[2];
    const float* Wneigh0  = (const float*)d_in[3];
    const float* b0       = (const float*)d_in[4];
    const float* Wself    = (const float*)d_in[5];
    const float* Wneigh   = (const float*)d_in[6];
    const float* bvec     = (const float*)d_in[7];
    const float* bn_gamma = (const float*)d_in[8];
    const float* bn_beta  = (const float*)d_in[9];
    const float* W1       = (const float*)d_in[10];
    const float* b1       = (const float*)d_in[11];
    const float* bng1     = (const float*)d_in[12];
    const float* bnb1     = (const float*)d_in[13];
    const float* W2       = (const float*)d_in[14];
    const float* b2       = (const float*)d_in[15];
    float* out = (float*)d_out;

    float *h, *hn, *agg, *z;
    cudaGetSymbolAddress((void**)&h,   g_h);
    cudaGetSymbolAddress((void**)&hn,  g_hn);
    cudaGetSymbolAddress((void**)&agg, g_agg);
    cudaGetSymbolAddress((void**)&z,   g_z);

    const int TB = 256;
    const int gN = (NN + TB - 1) / TB;
    const int gE = (EE + TB - 1) / TB;
    const dim3 gemmH(1, (NN + 127) / 128);  // NC=128 GEMMs
    const int norm4_128 = NN * HH / 4;
    const int gNorm128 = (norm4_128 + TB - 1) / TB;

    // ---- CSR + degree/denominator ----
    k_zero_deg<<<gN, TB>>>();
    k_count<<<gE, TB>>>(graph);
    k_scan1<<<(NN + 1023) / 1024, 1024>>>();
    k_scan2<<<1, 32>>>();
    k_scan3<<<gN, TB>>>();
    k_fill<<<gE, TB>>>(graph);

    // ---- layer 0 (K = 700) ----
    sgemm<128, 8><<<gemmH, 256>>>(inputs, Wneigh0, hn, NN, FIN, HH);
    k_aggregate<<<NN, HH>>>(hn, agg);
    sgemm<128, 8><<<gemmH, 256>>>(inputs, Wself0, hn, NN, FIN, HH);
    k_zero_stats<<<1, 256>>>();
    k_combine<<<(NN + 63) / 64, HH>>>(hn, agg, b0, NN, 64);
    k_finalize<<<1, HH>>>(bn_gamma, bn_beta, NN);
    k_normalize<<<gNorm128, TB>>>(hn, h, nullptr, norm4_128, HH / 4);

    // ---- layers 1..3 (K = 128) ----
    for (int l = 0; l < 3; l++) {
        const float* Wn = Wneigh + (size_t)l * HH * HH;
        const float* Ws = Wself  + (size_t)l * HH * HH;
        const float* bb = bvec + (size_t)l * HH;
        sgemm<128, 8><<<gemmH, 256>>>(h, Wn, hn, NN, HH, HH);
        k_aggregate<<<NN, HH>>>(hn, agg);
        sgemm<128, 8><<<gemmH, 256>>>(h, Ws, hn, NN, HH, HH);
        k_zero_stats<<<1, 256>>>();
        k_combine<<<(NN + 63) / 64, HH>>>(hn, agg, bb, NN, 64);
        k_finalize<<<1, HH>>>(bn_gamma + (size_t)(l + 1) * HH, bn_beta + (size_t)(l + 1) * HH, NN);
        k_normalize<<<gNorm128, TB>>>(hn, h, h, norm4_128, HH / 4);  // residual + relu, in place
    }

    // ---- head: z = BN(h @ W1 + b1) -> relu -> @ W2 + b2 ----
    sgemm<64, 4><<<dim3(1, (NN + 127) / 128), 256>>>(h, W1, z, NN, HH, 64);
    k_zero_stats<<<1, 256>>>();
    k_combine<<<(NN + 127) / 128, 64>>>(z, nullptr, b1, NN, 128);
    k_finalize<<<1, 64>>>(bng1, bnb1, NN);
    k_output<<<(NN * 32 + TB - 1) / TB, TB>>>(z, W2, b2, out);

    (void)in_sizes; (void)n_in; (void)out_size;
}

// round 3
// speedup vs baseline: 1.6119x; 1.6119x over previous
#include <cuda_runtime.h>
#include <cuda_bf16.h>
#include <math.h>
#include <stdint.h>

#define NN   100000
#define MPAD 100096
#define EE   1600000
#define FIN  700
#define K0P  704
#define HH   128
#define EPSV 1e-5f

// ---------------- scratch (static device globals; zero-init, no runtime alloc) ----
__device__ float g_h  [(size_t)NN * HH];
__device__ float g_hc [(size_t)NN * 256];        // [self(128) | neigh(128)] per row
__device__ float g_agg[(size_t)NN * HH];
__device__ float g_z  [(size_t)NN * 64];
__device__ float g_denom[NN];
__device__ int   g_deg[NN];
__device__ int   g_rowptr[NN + 1];
__device__ int   g_colidx[EE];
__device__ int   g_bsums[128];
__device__ __align__(16) float g_stats[256];
__device__ __align__(16) float g_ab[256];

// bf16 split operands
__device__ __nv_bfloat16 g_A0h[(size_t)MPAD * K0P];
__device__ __nv_bfloat16 g_A0l[(size_t)MPAD * K0P];
__device__ __nv_bfloat16 g_Ahh[(size_t)MPAD * HH];
__device__ __nv_bfloat16 g_Alo[(size_t)MPAD * HH];
__device__ __nv_bfloat16 g_B0h[256 * K0P];
__device__ __nv_bfloat16 g_B0l[256 * K0P];
__device__ __nv_bfloat16 g_BLh[3 * 256 * HH];
__device__ __nv_bfloat16 g_BLl[3 * 256 * HH];

// ---------------- helpers ------------------------------------------------------
__device__ __forceinline__ void split_bf16(float x, __nv_bfloat16& h, __nv_bfloat16& l) {
    h = __float2bfloat16(x);
    l = __float2bfloat16(x - __bfloat162float(h));
}
__device__ __forceinline__ void cp16(uint32_t s, const void* g) {
    asm volatile("cp.async.cg.shared.global [%0], [%1], 16;" :: "r"(s), "l"(g));
}
__device__ __forceinline__ void ldsm4(uint32_t& r0, uint32_t& r1, uint32_t& r2, uint32_t& r3, uint32_t a) {
    asm volatile("ldmatrix.sync.aligned.m8n8.x4.shared.b16 {%0,%1,%2,%3}, [%4];"
                 : "=r"(r0), "=r"(r1), "=r"(r2), "=r"(r3) : "r"(a));
}
__device__ __forceinline__ void mma16816(float* c, const uint32_t* a, const uint32_t* b) {
    asm volatile("mma.sync.aligned.m16n8k16.row.col.f32.bf16.bf16.f32 "
                 "{%0,%1,%2,%3}, {%4,%5,%6,%7}, {%8,%9}, {%0,%1,%2,%3};"
                 : "+f"(c[0]), "+f"(c[1]), "+f"(c[2]), "+f"(c[3])
                 : "r"(a[0]), "r"(a[1]), "r"(a[2]), "r"(a[3]), "r"(b[0]), "r"(b[1]));
}

// ---------------- CSR construction --------------------------------------------
__global__ void k_zero_deg() {
    int i = blockIdx.x * blockDim.x + threadIdx.x;
    if (i < NN) g_deg[i] = 0;
}
__global__ void k_count(const int* __restrict__ graph) {
    int e = blockIdx.x * blockDim.x + threadIdx.x;
    if (e < EE) atomicAdd(&g_deg[graph[2 * e + 1]], 1);
}
__global__ void k_scan1() {
    __shared__ int s[1024];
    int tid = threadIdx.x;
    int i = blockIdx.x * 1024 + tid;
    int v = (i < NN) ? g_deg[i] : 0;
    s[tid] = v;
    __syncthreads();
    #pragma unroll
    for (int off = 1; off < 1024; off <<= 1) {
        int t = (tid >= off) ? s[tid - off] : 0;
        __syncthreads();
        s[tid] += t;
        __syncthreads();
    }
    if (i < NN) g_rowptr[i + 1] = s[tid];
    if (tid == 1023) g_bsums[blockIdx.x] = s[1023];
}
__global__ void k_scan2() {
    if (threadIdx.x == 0) {
        const int nb = (NN + 1023) / 1024;
        int acc = 0;
        for (int i = 0; i < nb; i++) { int t = g_bsums[i]; g_bsums[i] = acc; acc += t; }
    }
}
__global__ void k_scan3() {
    int i = blockIdx.x * blockDim.x + threadIdx.x;
    if (i >= NN) return;
    g_rowptr[i + 1] += g_bsums[i >> 10];
    if (i == 0) g_rowptr[0] = 0;
    int d = g_deg[i];
    g_denom[i] = (float)((d > 1) ? d : 1);
    g_deg[i] = 0;
}
__global__ void k_fill(const int* __restrict__ graph) {
    int e = blockIdx.x * blockDim.x + threadIdx.x;
    if (e >= EE) return;
    int src = graph[2 * e + 0];
    int dst = graph[2 * e + 1];
    int pos = g_rowptr[dst] + atomicAdd(&g_deg[dst], 1);
    g_colidx[pos] = src;
}

// ---------------- operand conversion -------------------------------------------
__global__ void k_convW0(const float* __restrict__ Ws, const float* __restrict__ Wn) {
    int idx = blockIdx.x * blockDim.x + threadIdx.x;
    if (idx >= 256 * K0P) return;
    int n = idx / K0P, k = idx % K0P;
    float v = 0.f;
    if (k < FIN) v = (n < HH) ? Ws[(size_t)k * HH + n] : Wn[(size_t)k * HH + (n - HH)];
    split_bf16(v, g_B0h[idx], g_B0l[idx]);
}
__global__ void k_convWL(const float* __restrict__ Ws, const float* __restrict__ Wn) {
    int idx = blockIdx.x * blockDim.x + threadIdx.x;
    if (idx >= 3 * 256 * HH) return;
    int l = idx / (256 * HH);
    int rem = idx % (256 * HH);
    int n = rem / HH, k = rem % HH;
    float v = (n < HH) ? Ws[(size_t)l * HH * HH + k * HH + n]
                       : Wn[(size_t)l * HH * HH + k * HH + (n - HH)];
    split_bf16(v, g_BLh[idx], g_BLl[idx]);
}
__global__ void k_convA0(const float* __restrict__ inputs) {
    int i = blockIdx.x * blockDim.x + threadIdx.x;
    if (i >= NN * 176) return;
    int r = i / 176, q = i % 176;
    float4 v = make_float4(0.f, 0.f, 0.f, 0.f);
    if (q < 175) v = *reinterpret_cast<const float4*>(inputs + (size_t)r * FIN + q * 4);
    size_t off = (size_t)r * K0P + q * 4;
    __nv_bfloat16 h0, h1, h2, h3, l0, l1, l2, l3;
    split_bf16(v.x, h0, l0); split_bf16(v.y, h1, l1);
    split_bf16(v.z, h2, l2); split_bf16(v.w, h3, l3);
    *reinterpret_cast<__nv_bfloat162*>(g_A0h + off)     = __halves2bfloat162(h0, h1);
    *reinterpret_cast<__nv_bfloat162*>(g_A0h + off + 2) = __halves2bfloat162(h2, h3);
    *reinterpret_cast<__nv_bfloat162*>(g_A0l + off)     = __halves2bfloat162(l0, l1);
    *reinterpret_cast<__nv_bfloat162*>(g_A0l + off + 2) = __halves2bfloat162(l2, l3);
}

// ---------------- bf16 split-precision tensor GEMM -----------------------------
// C cols [bx*128, bx*128+128) = A[M][Kpad] @ Bcat[bx half]^T
// BM=128, BN=128, BK=16, 256 threads (8 warps, warp tile 64x32), 2-stage cp.async.
// smem per stage: 4 tiles (Ah, Al, Bh, Bl) of 128 rows x 24 halfs (48B stride).
#define TILE_B 6144
#define STAGE_B 24576
__global__ void __launch_bounds__(256) gemm_bf16(
    const __nv_bfloat16* __restrict__ Ah, const __nv_bfloat16* __restrict__ Al,
    const __nv_bfloat16* __restrict__ Bh0, const __nv_bfloat16* __restrict__ Bl0,
    float* __restrict__ C, int M, int Kpad, int NCs)
{
    __shared__ __align__(16) char smem[49152];
    const uint32_t sb = (uint32_t)__cvta_generic_to_shared(smem);
    const int tid = threadIdx.x;
    const int bx = blockIdx.x, by = blockIdx.y;
    const int row0 = by * 128;
    const __nv_bfloat16* Bh = Bh0 + (size_t)bx * 128 * Kpad;
    const __nv_bfloat16* Bl = Bl0 + (size_t)bx * 128 * Kpad;
    const int KT = Kpad >> 4;

    auto load_stage = [&](int kt) {
        uint32_t base = sb + (uint32_t)(kt & 1) * STAGE_B;
        int k0 = kt * 16;
        #pragma unroll
        for (int i = 0; i < 4; i++) {
            int c = tid + i * 256;          // 0..1023
            int tile = c >> 8;              // 0..3
            int c8 = c & 255;
            int r = c8 >> 1, q = c8 & 1;
            uint32_t so = base + (uint32_t)(tile * TILE_B + r * 48 + q * 16);
            const __nv_bfloat16* src;
            size_t goff;
            if (tile == 0)      { src = Ah; goff = (size_t)(row0 + r) * Kpad + k0 + q * 8; }
            else if (tile == 1) { src = Al; goff = (size_t)(row0 + r) * Kpad + k0 + q * 8; }
            else if (tile == 2) { src = Bh; goff = (size_t)r * Kpad + k0 + q * 8; }
            else                { src = Bl; goff = (size_t)r * Kpad + k0 + q * 8; }
            cp16(so, src + goff);
        }
        asm volatile("cp.async.commit_group;");
    };

    load_stage(0);
    load_stage(1);

    const int lane = tid & 31, w = tid >> 5;
    const int wm = w >> 2, wn = w & 3;           // 2 x 4 warp grid
    const int lr = lane >> 2, lc = lane & 3;
    const int mat = lane >> 3, r8 = lane & 7;

    float acc[4][4][4];
    #pragma unroll
    for (int a = 0; a < 4; a++)
        #pragma unroll
        for (int b = 0; b < 4; b++)
            #pragma unroll
            for (int d = 0; d < 4; d++) acc[a][b][d] = 0.f;

    for (int kt = 0; kt < KT; ++kt) {
        if (kt < KT - 1) asm volatile("cp.async.wait_group 1;");
        else             asm volatile("cp.async.wait_group 0;");
        __syncthreads();
        uint32_t base = sb + (uint32_t)(kt & 1) * STAGE_B;

        // B fragments: rows = n (warp covers wn*32 .. +32), cols = k (16)
        uint32_t bh[2][4], bl[2][4];
        #pragma unroll
        for (int p = 0; p < 2; p++) {
            int brow = wn * 32 + p * 16 + r8 + (mat >> 1) * 8;
            uint32_t addr = base + 2u * TILE_B + (uint32_t)(brow * 48 + ((mat & 1) * 8) * 2);
            ldsm4(bh[p][0], bh[p][1], bh[p][2], bh[p][3], addr);
            ldsm4(bl[p][0], bl[p][1], bl[p][2], bl[p][3], addr + TILE_B);
        }
        #pragma unroll
        for (int mf = 0; mf < 4; ++mf) {
            int arow = wm * 64 + mf * 16 + r8 + (mat & 1) * 8;
            uint32_t aaddr = base + (uint32_t)(arow * 48 + ((mat >> 1) * 8) * 2);
            uint32_t ahr[4], alr[4];
            ldsm4(ahr[0], ahr[1], ahr[2], ahr[3], aaddr);
            ldsm4(alr[0], alr[1], alr[2], alr[3], aaddr + TILE_B);
            #pragma unroll
            for (int nf = 0; nf < 4; ++nf) {
                const uint32_t* bhp = &bh[nf >> 1][(nf & 1) * 2];
                const uint32_t* blp = &bl[nf >> 1][(nf & 1) * 2];
                mma16816(acc[mf][nf], ahr, bhp);
                mma16816(acc[mf][nf], alr, bhp);
                mma16816(acc[mf][nf], ahr, blp);
            }
        }
        __syncthreads();
        if (kt + 2 < KT) load_stage(kt + 2);
    }

    #pragma unroll
    for (int mf = 0; mf < 4; ++mf) {
        #pragma unroll
        for (int nf = 0; nf < 4; ++nf) {
            int r = row0 + wm * 64 + mf * 16 + lr;
            int cc = bx * 128 + wn * 32 + nf * 8 + lc * 2;
            if (r < M)
                *reinterpret_cast<float2*>(C + (size_t)r * NCs + cc) =
                    make_float2(acc[mf][nf][0], acc[mf][nf][1]);
            if (r + 8 < M)
                *reinterpret_cast<float2*>(C + (size_t)(r + 8) * NCs + cc) =
                    make_float2(acc[mf][nf][2], acc[mf][nf][3]);
        }
    }
}

// ---------------- fp32 SGEMM (head only) ---------------------------------------
template <int BN, int TN>
__global__ __launch_bounds__(256) void sgemm(const float* __restrict__ A,
                                             const float* __restrict__ B,
                                             float* __restrict__ C,
                                             int M, int K, int NC) {
    constexpr int BM = 128, BK = 8, TM = 8;
    constexpr int TX = BN / TN;
    __shared__ float As[BK][BM];
    __shared__ float Bs[BK][BN];
    const int tid = threadIdx.x;
    const int tx = tid % TX;
    const int ty = tid / TX;
    const int row0 = blockIdx.y * BM;
    const int col0 = blockIdx.x * BN;
    float acc[TM][TN];
    #pragma unroll
    for (int i = 0; i < TM; i++)
        #pragma unroll
        for (int j = 0; j < TN; j++) acc[i][j] = 0.f;
    for (int kk = 0; kk < K; kk += BK) {
        {
            constexpr int NF4 = BM * BK / 4;
            #pragma unroll
            for (int t = tid; t < NF4; t += 256) {
                int r = t / (BK / 4);
                int q = t % (BK / 4);
                float4 v = make_float4(0.f, 0.f, 0.f, 0.f);
                int gr = row0 + r, gk = kk + q * 4;
                if (gr < M && gk < K)
                    v = *reinterpret_cast<const float4*>(A + (size_t)gr * K + gk);
                As[q * 4 + 0][r] = v.x; As[q * 4 + 1][r] = v.y;
                As[q * 4 + 2][r] = v.z; As[q * 4 + 3][r] = v.w;
            }
        }
        {
            constexpr int NF4 = BK * BN / 4;
            #pragma unroll
            for (int t = tid; t < NF4; t += 256) {
                int r = t / (BN / 4);
                int q = t % (BN / 4);
                float4 v = make_float4(0.f, 0.f, 0.f, 0.f);
                int gk = kk + r;
                if (gk < K)
                    v = *reinterpret_cast<const float4*>(B + (size_t)gk * NC + col0 + q * 4);
                *reinterpret_cast<float4*>(&Bs[r][q * 4]) = v;
            }
        }
        __syncthreads();
        #pragma unroll
        for (int k = 0; k < BK; k++) {
            float a[TM], b[TN];
            #pragma unroll
            for (int i = 0; i < TM; i++) a[i] = As[k][ty * TM + i];
            #pragma unroll
            for (int j = 0; j < TN; j++) b[j] = Bs[k][tx * TN + j];
            #pragma unroll
            for (int i = 0; i < TM; i++)
                #pragma unroll
                for (int j = 0; j < TN; j++) acc[i][j] = fmaf(a[i], b[j], acc[i][j]);
        }
        __syncthreads();
    }
    #pragma unroll
    for (int i = 0; i < TM; i++) {
        int gr = row0 + ty * TM + i;
        if (gr >= M) continue;
        #pragma unroll
        for (int j = 0; j < TN; j += 4) {
            float4 v = make_float4(acc[i][j], acc[i][j + 1], acc[i][j + 2], acc[i][j + 3]);
            *reinterpret_cast<float4*>(C + (size_t)gr * NC + col0 + tx * TN + j) = v;
        }
    }
}

// ---------------- neighbor aggregation (CSR gather) ----------------------------
__global__ void k_aggregate(const float* __restrict__ hn, int stride, float* __restrict__ agg) {
    int node = blockIdx.x;
    int c = threadIdx.x;
    int s = g_rowptr[node];
    int e = g_rowptr[node + 1];
    float acc = 0.f;
    int p = s;
    for (; p + 1 < e; p += 2) {
        int n0 = __ldg(&g_colidx[p]);
        int n1 = __ldg(&g_colidx[p + 1]);
        acc += __ldg(&hn[(size_t)n0 * stride + c]) + __ldg(&hn[(size_t)n1 * stride + c]);
    }
    if (p < e) acc += __ldg(&hn[(size_t)g_colidx[p] * stride + c]);
    agg[(size_t)node * HH + c] = acc / g_denom[node];
}

// ---------------- BN machinery --------------------------------------------------
__global__ void k_zero_stats() { g_stats[threadIdx.x] = 0.f; }

__global__ void k_combine2(float* __restrict__ pre, const float* __restrict__ agg,
                           const float* __restrict__ bias, int rows) {
    int c = threadIdx.x;
    int r0 = blockIdx.x * rows;
    int r1 = min(r0 + rows, NN);
    float bb = bias[c];
    float s = 0.f, s2 = 0.f;
    for (int r = r0; r < r1; r++) {
        float v = pre[(size_t)r * 256 + c] + bb + agg[(size_t)r * HH + c];
        pre[(size_t)r * 256 + c] = v;
        s += v;
        s2 += v * v;
    }
    atomicAdd(&g_stats[c], s);
    atomicAdd(&g_stats[HH + c], s2);
}

__global__ void k_combine(float* __restrict__ pre, const float* __restrict__ bias,
                          int M, int rows) {
    const int Hc = blockDim.x;
    int c = threadIdx.x;
    int r0 = blockIdx.x * rows;
    int r1 = min(r0 + rows, M);
    float bb = bias[c];
    float s = 0.f, s2 = 0.f;
    for (int r = r0; r < r1; r++) {
        float v = pre[(size_t)r * Hc + c] + bb;
        pre[(size_t)r * Hc + c] = v;
        s += v;
        s2 += v * v;
    }
    atomicAdd(&g_stats[c], s);
    atomicAdd(&g_stats[Hc + c], s2);
}

__global__ void k_finalize(const float* __restrict__ gamma, const float* __restrict__ beta, int M) {
    int c = threadIdx.x;
    int Hc = blockDim.x;
    float inv_m = 1.f / (float)M;
    float mean = g_stats[c] * inv_m;
    float var = g_stats[Hc + c] * inv_m - mean * mean;
    float a = gamma[c] * rsqrtf(var + EPSV);
    g_ab[c] = a;
    g_ab[Hc + c] = beta[c] - mean * a;
}

// BN + (residual) + ReLU; writes h fp32 AND bf16 hi/lo split for next GEMM
__global__ void k_norm_split(const float* __restrict__ pre, float* __restrict__ h,
                             const float* __restrict__ resid) {
    int i = blockIdx.x * blockDim.x + threadIdx.x;
    if (i >= NN * 32) return;
    int r = i >> 5, q = i & 31;
    float4 p = *reinterpret_cast<const float4*>(pre + (size_t)r * 256 + q * 4);
    float4 a = *reinterpret_cast<const float4*>(g_ab + q * 4);
    float4 b = *reinterpret_cast<const float4*>(g_ab + HH + q * 4);
    float4 v;
    v.x = fmaf(p.x, a.x, b.x); v.y = fmaf(p.y, a.y, b.y);
    v.z = fmaf(p.z, a.z, b.z); v.w = fmaf(p.w, a.w, b.w);
    if (resid) {
        float4 rr = *reinterpret_cast<const float4*>(resid + (size_t)r * HH + q * 4);
        v.x += rr.x; v.y += rr.y; v.z += rr.z; v.w += rr.w;
    }
    v.x = fmaxf(v.x, 0.f); v.y = fmaxf(v.y, 0.f);
    v.z = fmaxf(v.z, 0.f); v.w = fmaxf(v.w, 0.f);
    *reinterpret_cast<float4*>(h + (size_t)r * HH + q * 4) = v;
    size_t off = (size_t)r * HH + q * 4;
    __nv_bfloat16 h0, h1, h2, h3, l0, l1, l2, l3;
    split_bf16(v.x, h0, l0); split_bf16(v.y, h1, l1);
    split_bf16(v.z, h2, l2); split_bf16(v.w, h3, l3);
    *reinterpret_cast<__nv_bfloat162*>(g_Ahh + off)     = __halves2bfloat162(h0, h1);
    *reinterpret_cast<__nv_bfloat162*>(g_Ahh + off + 2) = __halves2bfloat162(h2, h3);
    *reinterpret_cast<__nv_bfloat162*>(g_Alo + off)     = __halves2bfloat162(l0, l1);
    *reinterpret_cast<__nv_bfloat162*>(g_Alo + off + 2) = __halves2bfloat162(l2, l3);
}

// final head: BN -> relu -> @W2 + b2, one warp per node
__global__ void k_output(const float* __restrict__ zpre, const float* __restrict__ W2,
                         const float* __restrict__ b2, float* __restrict__ out) {
    int gtid = blockIdx.x * blockDim.x + threadIdx.x;
    int node = gtid >> 5;
    int lane = gtid & 31;
    if (node >= NN) return;
    float acc = 0.f;
    #pragma unroll
    for (int j = lane; j < 64; j += 32) {
        float v = fmaf(zpre[(size_t)node * 64 + j], g_ab[j], g_ab[64 + j]);
        v = fmaxf(v, 0.f);
        acc += v * W2[j];
    }
    #pragma unroll
    for (int o = 16; o; o >>= 1) acc += __shfl_xor_sync(0xFFFFFFFFu, acc, o);
    if (lane == 0) out[node] = acc + b2[0];
}

// ---------------- host orchestration ------------------------------------------
extern "C" void kernel_launch(void* const* d_in, const int* in_sizes, int n_in,
                              void* d_out, int out_size) {
    const float* inputs   = (const float*)d_in[0];
    const int*   graph    = (const int*)  d_in[1];
    const float* Wself0   = (const float*)d_in[2];
    const float* Wneigh0  = (const float*)d_in[3];
    const float* b0       = (const float*)d_in[4];
    const float* Wself    = (const float*)d_in[5];
    const float* Wneigh   = (const float*)d_in[6];
    const float* bvec     = (const float*)d_in[7];
    const float* bn_gamma = (const float*)d_in[8];
    const float* bn_beta  = (const float*)d_in[9];
    const float* W1       = (const float*)d_in[10];
    const float* b1       = (const float*)d_in[11];
    const float* bng1     = (const float*)d_in[12];
    const float* bnb1     = (const float*)d_in[13];
    const float* W2       = (const float*)d_in[14];
    const float* b2       = (const float*)d_in[15];
    float* out = (float*)d_out;

    float *h, *hc, *agg, *z;
    __nv_bfloat16 *A0h, *A0l, *Ahh, *Alo, *B0h, *B0l, *BLh, *BLl;
    cudaGetSymbolAddress((void**)&h,   g_h);
    cudaGetSymbolAddress((void**)&hc,  g_hc);
    cudaGetSymbolAddress((void**)&agg, g_agg);
    cudaGetSymbolAddress((void**)&z,   g_z);
    cudaGetSymbolAddress((void**)&A0h, g_A0h);
    cudaGetSymbolAddress((void**)&A0l, g_A0l);
    cudaGetSymbolAddress((void**)&Ahh, g_Ahh);
    cudaGetSymbolAddress((void**)&Alo, g_Alo);
    cudaGetSymbolAddress((void**)&B0h, g_B0h);
    cudaGetSymbolAddress((void**)&B0l, g_B0l);
    cudaGetSymbolAddress((void**)&BLh, g_BLh);
    cudaGetSymbolAddress((void**)&BLl, g_BLl);

    const int TB = 256;
    const int gN = (NN + TB - 1) / TB;
    const int gE = (EE + TB - 1) / TB;
    const dim3 gemmGrid(2, (NN + 127) / 128);
    const int gNorm = (NN * 32 + TB - 1) / TB;

    // ---- CSR ----
    k_zero_deg<<<gN, TB>>>();
    k_count<<<gE, TB>>>(graph);
    k_scan1<<<(NN + 1023) / 1024, 1024>>>();
    k_scan2<<<1, 32>>>();
    k_scan3<<<gN, TB>>>();
    k_fill<<<gE, TB>>>(graph);

    // ---- operand conversion ----
    k_convW0<<<(256 * K0P + TB - 1) / TB, TB>>>(Wself0, Wneigh0);
    k_convWL<<<(3 * 256 * HH + TB - 1) / TB, TB>>>(Wself, Wneigh);
    k_convA0<<<(NN * 176 + TB - 1) / TB, TB>>>(inputs);

    // ---- layer 0 ----
    gemm_bf16<<<gemmGrid, 256>>>(A0h, A0l, B0h, B0l, hc, NN, K0P, 256);
    k_aggregate<<<NN, HH>>>(hc + HH, 256, agg);
    k_zero_stats<<<1, 256>>>();
    k_combine2<<<(NN + 63) / 64, HH>>>(hc, agg, b0, 64);
    k_finalize<<<1, HH>>>(bn_gamma, bn_beta, NN);
    k_norm_split<<<gNorm, TB>>>(hc, h, nullptr);

    // ---- layers 1..3 ----
    for (int l = 0; l < 3; l++) {
        gemm_bf16<<<gemmGrid, 256>>>(Ahh, Alo,
                                     BLh + (size_t)l * 256 * HH,
                                     BLl + (size_t)l * 256 * HH,
                                     hc, NN, HH, 256);
        k_aggregate<<<NN, HH>>>(hc + HH, 256, agg);
        k_zero_stats<<<1, 256>>>();
        k_combine2<<<(NN + 63) / 64, HH>>>(hc, agg, bvec + (size_t)l * HH, 64);
        k_finalize<<<1, HH>>>(bn_gamma + (size_t)(l + 1) * HH, bn_beta + (size_t)(l + 1) * HH, NN);
        k_norm_split<<<gNorm, TB>>>(hc, h, h);
    }

    // ---- head ----
    sgemm<64, 4><<<dim3(1, (NN + 127) / 128), 256>>>(h, W1, z, NN, HH, 64);
    k_zero_stats<<<1, 256>>>();
    k_combine<<<(NN + 127) / 128, 64>>>(z, b1, NN, 128);
    k_finalize<<<1, 64>>>(bng1, bnb1, NN);
    k_output<<<(NN * 32 + TB - 1) / TB, TB>>>(z, W2, b2, out);

    (void)in_sizes; (void)n_in; (void)out_size;
}

// round 4
// speedup vs baseline: 1.6441x; 1.0200x over previous
#include <cuda_runtime.h>
#include <cuda_bf16.h>
#include <math.h>
#include <stdint.h>

#define NN   100000
#define EE   1600000
#define FIN  700
#define K0P  704
#define HH   128
#define EPSV 1e-5f

// ---------------- scratch (static device globals; zero-init, no runtime alloc) ----
__device__ float g_h  [(size_t)NN * HH];
__device__ float g_hc [(size_t)NN * 256];        // [self(128) | neigh(128)] per row
__device__ float g_z  [(size_t)NN * 64];
__device__ float g_denom[NN];
__device__ int   g_deg[NN];
__device__ int   g_rowptr[NN + 1];
__device__ int   g_colidx[EE];
__device__ int   g_bsums[128];
__device__ __align__(16) float g_stats[256];
__device__ __align__(16) float g_ab[256];

// bf16 split weights only (A operands are split in-GEMM now)
__device__ __nv_bfloat16 g_B0h[256 * K0P];
__device__ __nv_bfloat16 g_B0l[256 * K0P];
__device__ __nv_bfloat16 g_BLh[3 * 256 * HH];
__device__ __nv_bfloat16 g_BLl[3 * 256 * HH];

// ---------------- helpers ------------------------------------------------------
__device__ __forceinline__ void split_bf16(float x, __nv_bfloat16& h, __nv_bfloat16& l) {
    h = __float2bfloat16(x);
    l = __float2bfloat16(x - __bfloat162float(h));
}
__device__ __forceinline__ uint32_t pkbf2(__nv_bfloat16 a, __nv_bfloat16 b) {
    __nv_bfloat162 t = __halves2bfloat162(a, b);
    return *reinterpret_cast<uint32_t*>(&t);
}
__device__ __forceinline__ void cp16(uint32_t s, const void* g) {
    asm volatile("cp.async.cg.shared.global [%0], [%1], 16;" :: "r"(s), "l"(g));
}
__device__ __forceinline__ void ldsm4(uint32_t& r0, uint32_t& r1, uint32_t& r2, uint32_t& r3, uint32_t a) {
    asm volatile("ldmatrix.sync.aligned.m8n8.x4.shared.b16 {%0,%1,%2,%3}, [%4];"
                 : "=r"(r0), "=r"(r1), "=r"(r2), "=r"(r3) : "r"(a));
}
__device__ __forceinline__ void mma16816(float* c, const uint32_t* a, const uint32_t* b) {
    asm volatile("mma.sync.aligned.m16n8k16.row.col.f32.bf16.bf16.f32 "
                 "{%0,%1,%2,%3}, {%4,%5,%6,%7}, {%8,%9}, {%0,%1,%2,%3};"
                 : "+f"(c[0]), "+f"(c[1]), "+f"(c[2]), "+f"(c[3])
                 : "r"(a[0]), "r"(a[1]), "r"(a[2]), "r"(a[3]), "r"(b[0]), "r"(b[1]));
}

// ---------------- CSR construction --------------------------------------------
__global__ void k_zero_deg() {
    int i = blockIdx.x * blockDim.x + threadIdx.x;
    if (i < NN) g_deg[i] = 0;
}
__global__ void k_count(const int* __restrict__ graph) {
    int e = blockIdx.x * blockDim.x + threadIdx.x;
    if (e < EE) atomicAdd(&g_deg[graph[2 * e + 1]], 1);
}
__global__ void k_scan1() {
    __shared__ int s[1024];
    int tid = threadIdx.x;
    int i = blockIdx.x * 1024 + tid;
    int v = (i < NN) ? g_deg[i] : 0;
    s[tid] = v;
    __syncthreads();
    #pragma unroll
    for (int off = 1; off < 1024; off <<= 1) {
        int t = (tid >= off) ? s[tid - off] : 0;
        __syncthreads();
        s[tid] += t;
        __syncthreads();
    }
    if (i < NN) g_rowptr[i + 1] = s[tid];
    if (tid == 1023) g_bsums[blockIdx.x] = s[1023];
}
__global__ void k_scan2() {
    if (threadIdx.x == 0) {
        const int nb = (NN + 1023) / 1024;
        int acc = 0;
        for (int i = 0; i < nb; i++) { int t = g_bsums[i]; g_bsums[i] = acc; acc += t; }
    }
}
__global__ void k_scan3() {
    int i = blockIdx.x * blockDim.x + threadIdx.x;
    if (i >= NN) return;
    g_rowptr[i + 1] += g_bsums[i >> 10];
    if (i == 0) g_rowptr[0] = 0;
    int d = g_deg[i];
    g_denom[i] = (float)((d > 1) ? d : 1);
    g_deg[i] = 0;
}
__global__ void k_fill(const int* __restrict__ graph) {
    int e = blockIdx.x * blockDim.x + threadIdx.x;
    if (e >= EE) return;
    int src = graph[2 * e + 0];
    int dst = graph[2 * e + 1];
    int pos = g_rowptr[dst] + atomicAdd(&g_deg[dst], 1);
    g_colidx[pos] = src;
}

// ---------------- weight conversion --------------------------------------------
__global__ void k_convW0(const float* __restrict__ Ws, const float* __restrict__ Wn) {
    int idx = blockIdx.x * blockDim.x + threadIdx.x;
    if (idx >= 256 * K0P) return;
    int n = idx / K0P, k = idx % K0P;
    float v = 0.f;
    if (k < FIN) v = (n < HH) ? Ws[(size_t)k * HH + n] : Wn[(size_t)k * HH + (n - HH)];
    split_bf16(v, g_B0h[idx], g_B0l[idx]);
}
__global__ void k_convWL(const float* __restrict__ Ws, const float* __restrict__ Wn) {
    int idx = blockIdx.x * blockDim.x + threadIdx.x;
    if (idx >= 3 * 256 * HH) return;
    int l = idx / (256 * HH);
    int rem = idx % (256 * HH);
    int n = rem / HH, k = rem % HH;
    float v = (n < HH) ? Ws[(size_t)l * HH * HH + k * HH + n]
                       : Wn[(size_t)l * HH * HH + k * HH + (n - HH)];
    split_bf16(v, g_BLh[idx], g_BLl[idx]);
}

// ---------------- split-precision tensor GEMM, fp32 A fed in-kernel ------------
// C cols [bx*128, bx*128+128) = A[M][K](fp32) @ Bcat[bx half]^T (bf16 hi/lo)
// BM=128, BN=128, BK=16, 256 threads, 2-stage; A split to bf16 hi/lo in-register.
// Stage layout: [Ah 6K][Al 6K][Bh 6K][Bl 6K] (rows padded to 48B).
#define TILE_B 6144
#define STAGE_B 24576
__global__ void __launch_bounds__(256) gemm_split(
    const float* __restrict__ A, int K, int Kpad,
    const __nv_bfloat16* __restrict__ Bh0, const __nv_bfloat16* __restrict__ Bl0,
    float* __restrict__ C, int M, int NCs)
{
    __shared__ __align__(16) char smem[49152];
    const uint32_t sb = (uint32_t)__cvta_generic_to_shared(smem);
    const int tid = threadIdx.x;
    const int bx = blockIdx.x, by = blockIdx.y;
    const int row0 = by * 128;
    const __nv_bfloat16* Bh = Bh0 + (size_t)bx * 128 * Kpad;
    const __nv_bfloat16* Bl = Bl0 + (size_t)bx * 128 * Kpad;
    const int KT = Kpad >> 4;

    const int ar = tid >> 1, aq = tid & 1;   // A granule: row ar, 8-float half aq
    const int agr = row0 + ar;
    const float* Arow = A + (size_t)agr * K;

    float4 hv0, hv1;   // held tile (kt+1)
    float4 nv0, nv1;   // newly loading tile (kt+2)

    auto ldgA = [&](int kt, float4& v0, float4& v1) {
        v0 = make_float4(0.f, 0.f, 0.f, 0.f);
        v1 = v0;
        int kb = kt * 16 + aq * 8;
        if (agr < M) {
            if (kb + 3 < K) v0 = *reinterpret_cast<const float4*>(Arow + kb);
            if (kb + 7 < K) v1 = *reinterpret_cast<const float4*>(Arow + kb + 4);
        }
    };
    auto stsA = [&](int stage, float4 v0, float4 v1) {
        float f[8] = {v0.x, v0.y, v0.z, v0.w, v1.x, v1.y, v1.z, v1.w};
        __nv_bfloat16 hh[8], ll[8];
        #pragma unroll
        for (int i = 0; i < 8; i++) split_bf16(f[i], hh[i], ll[i]);
        uint4 hvv, lvv;
        hvv.x = pkbf2(hh[0], hh[1]); hvv.y = pkbf2(hh[2], hh[3]);
        hvv.z = pkbf2(hh[4], hh[5]); hvv.w = pkbf2(hh[6], hh[7]);
        lvv.x = pkbf2(ll[0], ll[1]); lvv.y = pkbf2(ll[2], ll[3]);
        lvv.z = pkbf2(ll[4], ll[5]); lvv.w = pkbf2(ll[6], ll[7]);
        char* dst = smem + stage * STAGE_B + ar * 48 + aq * 16;
        *reinterpret_cast<uint4*>(dst) = hvv;
        *reinterpret_cast<uint4*>(dst + TILE_B) = lvv;
    };
    auto cpB = [&](int kt) {
        uint32_t base = sb + (uint32_t)(kt & 1) * STAGE_B + 2u * TILE_B;
        int r = tid >> 1, q = tid & 1;
        uint32_t so = base + (uint32_t)(r * 48 + q * 16);
        size_t gb = (size_t)r * Kpad + kt * 16 + q * 8;
        cp16(so, Bh + gb);
        cp16(so + TILE_B, Bl + gb);
        asm volatile("cp.async.commit_group;");
    };

    // prologue
    {
        float4 a0, a1;
        ldgA(0, a0, a1);
        ldgA(1, hv0, hv1);
        cpB(0);
        cpB(1);
        stsA(0, a0, a1);
    }

    const int lane = tid & 31, w = tid >> 5;
    const int wm = w >> 2, wn = w & 3;
    const int lr = lane >> 2, lc = lane & 3;
    const int mat = lane >> 3, r8 = lane & 7;

    float acc[4][4][4];
    #pragma unroll
    for (int a = 0; a < 4; a++)
        #pragma unroll
        for (int b = 0; b < 4; b++)
            #pragma unroll
            for (int d = 0; d < 4; d++) acc[a][b][d] = 0.f;

    for (int kt = 0; kt < KT; ++kt) {
        if (kt < KT - 1) asm volatile("cp.async.wait_group 1;");
        else             asm volatile("cp.async.wait_group 0;");
        __syncthreads();

        // feed stage s^1 with A(kt+1); start LDG of A(kt+2)
        if (kt + 1 < KT) stsA((kt + 1) & 1, hv0, hv1);
        if (kt + 2 < KT) ldgA(kt + 2, nv0, nv1);

        uint32_t base = sb + (uint32_t)(kt & 1) * STAGE_B;

        uint32_t bh[2][4], bl[2][4];
        #pragma unroll
        for (int p = 0; p < 2; p++) {
            int brow = wn * 32 + p * 16 + r8 + (mat >> 1) * 8;
            uint32_t addr = base + 2u * TILE_B + (uint32_t)(brow * 48 + ((mat & 1) * 8) * 2);
            ldsm4(bh[p][0], bh[p][1], bh[p][2], bh[p][3], addr);
            ldsm4(bl[p][0], bl[p][1], bl[p][2], bl[p][3], addr + TILE_B);
        }
        #pragma unroll
        for (int mf = 0; mf < 4; ++mf) {
            int arow = wm * 64 + mf * 16 + r8 + (mat & 1) * 8;
            uint32_t aaddr = base + (uint32_t)(arow * 48 + ((mat >> 1) * 8) * 2);
            uint32_t ahr[4], alr[4];
            ldsm4(ahr[0], ahr[1], ahr[2], ahr[3], aaddr);
            ldsm4(alr[0], alr[1], alr[2], alr[3], aaddr + TILE_B);
            #pragma unroll
            for (int nf = 0; nf < 4; ++nf) {
                const uint32_t* bhp = &bh[nf >> 1][(nf & 1) * 2];
                const uint32_t* blp = &bl[nf >> 1][(nf & 1) * 2];
                mma16816(acc[mf][nf], ahr, bhp);
                mma16816(acc[mf][nf], alr, bhp);
                mma16816(acc[mf][nf], ahr, blp);
            }
        }
        __syncthreads();
        if (kt + 2 < KT) {
            cpB(kt + 2);             // refills stage kt&1 (reads done)
            hv0 = nv0; hv1 = nv1;
        }
    }

    #pragma unroll
    for (int mf = 0; mf < 4; ++mf) {
        #pragma unroll
        for (int nf = 0; nf < 4; ++nf) {
            int r = row0 + wm * 64 + mf * 16 + lr;
            int cc = bx * 128 + wn * 32 + nf * 8 + lc * 2;
            if (r < M)
                *reinterpret_cast<float2*>(C + (size_t)r * NCs + cc) =
                    make_float2(acc[mf][nf][0], acc[mf][nf][1]);
            if (r + 8 < M)
                *reinterpret_cast<float2*>(C + (size_t)(r + 8) * NCs + cc) =
                    make_float2(acc[mf][nf][2], acc[mf][nf][3]);
        }
    }
}

// ---------------- fp32 SGEMM (head only) ---------------------------------------
template <int BN, int TN>
__global__ __launch_bounds__(256) void sgemm(const float* __restrict__ A,
                                             const float* __restrict__ B,
                                             float* __restrict__ C,
                                             int M, int K, int NC) {
    constexpr int BM = 128, BK = 8, TM = 8;
    constexpr int TX = BN / TN;
    __shared__ float As[BK][BM];
    __shared__ float Bs[BK][BN];
    const int tid = threadIdx.x;
    const int tx = tid % TX;
    const int ty = tid / TX;
    const int row0 = blockIdx.y * BM;
    const int col0 = blockIdx.x * BN;
    float acc[TM][TN];
    #pragma unroll
    for (int i = 0; i < TM; i++)
        #pragma unroll
        for (int j = 0; j < TN; j++) acc[i][j] = 0.f;
    for (int kk = 0; kk < K; kk += BK) {
        {
            constexpr int NF4 = BM * BK / 4;
            #pragma unroll
            for (int t = tid; t < NF4; t += 256) {
                int r = t / (BK / 4);
                int q = t % (BK / 4);
                float4 v = make_float4(0.f, 0.f, 0.f, 0.f);
                int gr = row0 + r, gk = kk + q * 4;
                if (gr < M && gk < K)
                    v = *reinterpret_cast<const float4*>(A + (size_t)gr * K + gk);
                As[q * 4 + 0][r] = v.x; As[q * 4 + 1][r] = v.y;
                As[q * 4 + 2][r] = v.z; As[q * 4 + 3][r] = v.w;
            }
        }
        {
            constexpr int NF4 = BK * BN / 4;
            #pragma unroll
            for (int t = tid; t < NF4; t += 256) {
                int r = t / (BN / 4);
                int q = t % (BN / 4);
                float4 v = make_float4(0.f, 0.f, 0.f, 0.f);
                int gk = kk + r;
                if (gk < K)
                    v = *reinterpret_cast<const float4*>(B + (size_t)gk * NC + col0 + q * 4);
                *reinterpret_cast<float4*>(&Bs[r][q * 4]) = v;
            }
        }
        __syncthreads();
        #pragma unroll
        for (int k = 0; k < BK; k++) {
            float a[TM], b[TN];
            #pragma unroll
            for (int i = 0; i < TM; i++) a[i] = As[k][ty * TM + i];
            #pragma unroll
            for (int j = 0; j < TN; j++) b[j] = Bs[k][tx * TN + j];
            #pragma unroll
            for (int i = 0; i < TM; i++)
                #pragma unroll
                for (int j = 0; j < TN; j++) acc[i][j] = fmaf(a[i], b[j], acc[i][j]);
        }
        __syncthreads();
    }
    #pragma unroll
    for (int i = 0; i < TM; i++) {
        int gr = row0 + ty * TM + i;
        if (gr >= M) continue;
        #pragma unroll
        for (int j = 0; j < TN; j += 4) {
            float4 v = make_float4(acc[i][j], acc[i][j + 1], acc[i][j + 2], acc[i][j + 3]);
            *reinterpret_cast<float4*>(C + (size_t)gr * NC + col0 + tx * TN + j) = v;
        }
    }
}

// ---------------- fused CSR gather + bias combine + BN stats --------------------
// per node: self(hc col c) + bias + gather(neigh half of hc)/denom -> hc self col,
// accumulate column sum/sumsq into g_stats.
__global__ void k_aggcomb(float* __restrict__ hc, const float* __restrict__ bias, int rows) {
    int c = threadIdx.x;                 // 128 threads = columns
    int r0 = blockIdx.x * rows;
    int r1 = min(r0 + rows, NN);
    float bb = bias[c];
    float s = 0.f, s2 = 0.f;
    for (int node = r0; node < r1; node++) {
        int p = g_rowptr[node];
        int e = g_rowptr[node + 1];
        float acc = 0.f;
        for (; p + 1 < e; p += 2) {
            int n0 = __ldg(&g_colidx[p]);
            int n1 = __ldg(&g_colidx[p + 1]);
            acc += __ldg(&hc[(size_t)n0 * 256 + HH + c]) + __ldg(&hc[(size_t)n1 * 256 + HH + c]);
        }
        if (p < e) acc += __ldg(&hc[(size_t)g_colidx[p] * 256 + HH + c]);
        float v = hc[(size_t)node * 256 + c] + bb + acc / g_denom[node];
        hc[(size_t)node * 256 + c] = v;
        s += v;
        s2 += v * v;
    }
    atomicAdd(&g_stats[c], s);
    atomicAdd(&g_stats[HH + c], s2);
}

// head: pre stride == blockDim.x, no agg
__global__ void k_combine(float* __restrict__ pre, const float* __restrict__ bias,
                          int M, int rows) {
    const int Hc = blockDim.x;
    int c = threadIdx.x;
    int r0 = blockIdx.x * rows;
    int r1 = min(r0 + rows, M);
    float bb = bias[c];
    float s = 0.f, s2 = 0.f;
    for (int r = r0; r < r1; r++) {
        float v = pre[(size_t)r * Hc + c] + bb;
        pre[(size_t)r * Hc + c] = v;
        s += v;
        s2 += v * v;
    }
    atomicAdd(&g_stats[c], s);
    atomicAdd(&g_stats[Hc + c], s2);
}

// compute BN scale/offset, then self-zero stats for the next accumulation
__global__ void k_finalize(const float* __restrict__ gamma, const float* __restrict__ beta, int M) {
    int c = threadIdx.x;
    int Hc = blockDim.x;
    float inv_m = 1.f / (float)M;
    float mean = g_stats[c] * inv_m;
    float var = g_stats[Hc + c] * inv_m - mean * mean;
    float a = gamma[c] * rsqrtf(var + EPSV);
    g_ab[c] = a;
    g_ab[Hc + c] = beta[c] - mean * a;
    g_stats[c] = 0.f;
    g_stats[Hc + c] = 0.f;
}

// BN + (residual) + ReLU -> h (fp32 only; GEMM splits in-kernel now)
__global__ void k_norm(const float* __restrict__ pre, float* __restrict__ h,
                       const float* __restrict__ resid) {
    int i = blockIdx.x * blockDim.x + threadIdx.x;
    if (i >= NN * 32) return;
    int r = i >> 5, q = i & 31;
    float4 p = *reinterpret_cast<const float4*>(pre + (size_t)r * 256 + q * 4);
    float4 a = *reinterpret_cast<const float4*>(g_ab + q * 4);
    float4 b = *reinterpret_cast<const float4*>(g_ab + HH + q * 4);
    float4 v;
    v.x = fmaf(p.x, a.x, b.x); v.y = fmaf(p.y, a.y, b.y);
    v.z = fmaf(p.z, a.z, b.z); v.w = fmaf(p.w, a.w, b.w);
    if (resid) {
        float4 rr = *reinterpret_cast<const float4*>(resid + (size_t)r * HH + q * 4);
        v.x += rr.x; v.y += rr.y; v.z += rr.z; v.w += rr.w;
    }
    v.x = fmaxf(v.x, 0.f); v.y = fmaxf(v.y, 0.f);
    v.z = fmaxf(v.z, 0.f); v.w = fmaxf(v.w, 0.f);
    *reinterpret_cast<float4*>(h + (size_t)r * HH + q * 4) = v;
}

// final head: BN -> relu -> @W2 + b2, one warp per node
__global__ void k_output(const float* __restrict__ zpre, const float* __restrict__ W2,
                         const float* __restrict__ b2, float* __restrict__ out) {
    int gtid = blockIdx.x * blockDim.x + threadIdx.x;
    int node = gtid >> 5;
    int lane = gtid & 31;
    if (node >= NN) return;
    float acc = 0.f;
    #pragma unroll
    for (int j = lane; j < 64; j += 32) {
        float v = fmaf(zpre[(size_t)node * 64 + j], g_ab[j], g_ab[64 + j]);
        v = fmaxf(v, 0.f);
        acc += v * W2[j];
    }
    #pragma unroll
    for (int o = 16; o; o >>= 1) acc += __shfl_xor_sync(0xFFFFFFFFu, acc, o);
    if (lane == 0) out[node] = acc + b2[0];
}

// ---------------- host orchestration ------------------------------------------
extern "C" void kernel_launch(void* const* d_in, const int* in_sizes, int n_in,
                              void* d_out, int out_size) {
    const float* inputs   = (const float*)d_in[0];
    const int*   graph    = (const int*)  d_in[1];
    const float* Wself0   = (const float*)d_in[2];
    const float* Wneigh0  = (const float*)d_in[3];
    const float* b0       = (const float*)d_in[4];
    const float* Wself    = (const float*)d_in[5];
    const float* Wneigh   = (const float*)d_in[6];
    const float* bvec     = (const float*)d_in[7];
    const float* bn_gamma = (const float*)d_in[8];
    const float* bn_beta  = (const float*)d_in[9];
    const float* W1       = (const float*)d_in[10];
    const float* b1       = (const float*)d_in[11];
    const float* bng1     = (const float*)d_in[12];
    const float* bnb1     = (const float*)d_in[13];
    const float* W2       = (const float*)d_in[14];
    const float* b2       = (const float*)d_in[15];
    float* out = (float*)d_out;

    float *h, *hc, *z;
    __nv_bfloat16 *B0h, *B0l, *BLh, *BLl;
    cudaGetSymbolAddress((void**)&h,   g_h);
    cudaGetSymbolAddress((void**)&hc,  g_hc);
    cudaGetSymbolAddress((void**)&z,   g_z);
    cudaGetSymbolAddress((void**)&B0h, g_B0h);
    cudaGetSymbolAddress((void**)&B0l, g_B0l);
    cudaGetSymbolAddress((void**)&BLh, g_BLh);
    cudaGetSymbolAddress((void**)&BLl, g_BLl);

    const int TB = 256;
    const int gN = (NN + TB - 1) / TB;
    const int gE = (EE + TB - 1) / TB;
    const dim3 gemmGrid(2, (NN + 127) / 128);
    const int gNorm = (NN * 32 + TB - 1) / TB;

    // ---- CSR ----
    k_zero_deg<<<gN, TB>>>();
    k_count<<<gE, TB>>>(graph);
    k_scan1<<<(NN + 1023) / 1024, 1024>>>();
    k_scan2<<<1, 32>>>();
    k_scan3<<<gN, TB>>>();
    k_fill<<<gE, TB>>>(graph);

    // ---- weight conversion (tiny) ----
    k_convW0<<<(256 * K0P + TB - 1) / TB, TB>>>(Wself0, Wneigh0);
    k_convWL<<<(3 * 256 * HH + TB - 1) / TB, TB>>>(Wself, Wneigh);

    // ---- layer 0 (A = fp32 inputs, K=700, Kpad=704) ----
    gemm_split<<<gemmGrid, 256>>>(inputs, FIN, K0P, B0h, B0l, hc, NN, 256);
    k_aggcomb<<<(NN + 63) / 64, HH>>>(hc, b0, 64);
    k_finalize<<<1, HH>>>(bn_gamma, bn_beta, NN);
    k_norm<<<gNorm, TB>>>(hc, h, nullptr);

    // ---- layers 1..3 (A = fp32 h, K=128) ----
    for (int l = 0; l < 3; l++) {
        gemm_split<<<gemmGrid, 256>>>(h, HH, HH,
                                      BLh + (size_t)l * 256 * HH,
                                      BLl + (size_t)l * 256 * HH,
                                      hc, NN, 256);
        k_aggcomb<<<(NN + 63) / 64, HH>>>(hc, bvec + (size_t)l * HH, 64);
        k_finalize<<<1, HH>>>(bn_gamma + (size_t)(l + 1) * HH, bn_beta + (size_t)(l + 1) * HH, NN);
        k_norm<<<gNorm, TB>>>(hc, h, h);
    }

    // ---- head ----
    sgemm<64, 4><<<dim3(1, (NN + 127) / 128), 256>>>(h, W1, z, NN, HH, 64);
    k_combine<<<(NN + 127) / 128, 64>>>(z, b1, NN, 128);
    k_finalize<<<1, 64>>>(bng1, bnb1, NN);
    k_output<<<(NN * 32 + TB - 1) / TB, TB>>>(z, W2, b2, out);

    (void)in_sizes; (void)n_in; (void)out_size;
}